// round 2
// baseline (speedup 1.0000x reference)
#include <cuda_runtime.h>
#include <math.h>
#include <stdint.h>

// Problem constants
#define TT   4096      // tokens = B*S
#define DD   1024      // model dim
#define EE   8         // experts
#define FF   4096      // ffn dim
#define CAP  512       // expert capacity

// ---------------- scratch (device globals; no allocation allowed) ------------
__device__ float g_gate[TT];
__device__ int   g_expert[TT];
__device__ int   g_slot[TT];
__device__ int   g_token_of[EE * CAP];
__device__ float g_expert_in[(size_t)EE * CAP * DD];   // 16.8 MB
__device__ float g_h[(size_t)EE * CAP * FF];           // 67 MB

// ---------------- init: zero d_out + expert_in, token_of = -1 ----------------
__global__ void init_kernel(float* __restrict__ out) {
    int i = blockIdx.x * blockDim.x + threadIdx.x;   // exactly T*D/4 threads
    float4 z = make_float4(0.f, 0.f, 0.f, 0.f);
    ((float4*)out)[i] = z;
    ((float4*)g_expert_in)[i] = z;
    if (i < EE * CAP) g_token_of[i] = -1;
}

// ---------------- router: logits -> gate, argmax ----------------
__global__ void router_kernel(const float* __restrict__ x,
                              const float* __restrict__ wr,
                              const float* __restrict__ br) {
    int t = blockIdx.x;
    const float* xt = x + (size_t)t * DD;
    float acc[EE];
#pragma unroll
    for (int e = 0; e < EE; e++) acc[e] = 0.f;

    for (int d = threadIdx.x; d < DD; d += blockDim.x) {
        float xv = xt[d];
        const float4* w = (const float4*)(wr + (size_t)d * EE);
        float4 w0 = w[0], w1 = w[1];
        acc[0] += xv * w0.x; acc[1] += xv * w0.y;
        acc[2] += xv * w0.z; acc[3] += xv * w0.w;
        acc[4] += xv * w1.x; acc[5] += xv * w1.y;
        acc[6] += xv * w1.z; acc[7] += xv * w1.w;
    }
#pragma unroll
    for (int e = 0; e < EE; e++)
#pragma unroll
        for (int o = 16; o > 0; o >>= 1)
            acc[e] += __shfl_down_sync(0xffffffffu, acc[e], o);

    __shared__ float sacc[4][EE];
    int warp = threadIdx.x >> 5, lane = threadIdx.x & 31;
    if (lane == 0) {
#pragma unroll
        for (int e = 0; e < EE; e++) sacc[warp][e] = acc[e];
    }
    __syncthreads();
    if (threadIdx.x == 0) {
        float l[EE];
#pragma unroll
        for (int e = 0; e < EE; e++)
            l[e] = sacc[0][e] + sacc[1][e] + sacc[2][e] + sacc[3][e] + br[e];
        float m = l[0]; int am = 0;
#pragma unroll
        for (int e = 1; e < EE; e++) if (l[e] > m) { m = l[e]; am = e; }
        float s = 0.f;
#pragma unroll
        for (int e = 0; e < EE; e++) s += expf(l[e] - m);
        g_gate[t]   = 1.f / s;      // = softmax max prob
        g_expert[t] = am;
    }
}

// ---------------- scan: token-order positions per expert ----------------
__global__ void scan_kernel() {
    __shared__ int scnt[256][EE];
    int tid = threadIdx.x;
    int cnt[EE];
#pragma unroll
    for (int e = 0; e < EE; e++) cnt[e] = 0;
    int base_t = tid * 16;
    for (int i = 0; i < 16; i++) cnt[g_expert[base_t + i]]++;
#pragma unroll
    for (int e = 0; e < EE; e++) scnt[tid][e] = cnt[e];
    __syncthreads();
    if (tid < EE) {
        int run = 0;
        for (int i = 0; i < 256; i++) {
            int v = scnt[i][tid]; scnt[i][tid] = run; run += v;
        }
    }
    __syncthreads();
    int pos[EE];
#pragma unroll
    for (int e = 0; e < EE; e++) pos[e] = scnt[tid][e];
    for (int i = 0; i < 16; i++) {
        int t = base_t + i;
        int e = g_expert[t];
        int p = ++pos[e];                 // 1-based position (reference quirk)
        if (p < CAP) {                    // pos < C keeps it
            g_slot[t] = p;
            g_token_of[e * CAP + p] = t;
        } else {
            g_slot[t] = -1;
        }
    }
}

// ---------------- gather: expert_in[e, slot] = gate * x[t] ----------------
__global__ void gather_kernel(const float* __restrict__ x) {
    int t = blockIdx.x;
    int s = g_slot[t];
    if (s < 0) return;
    int e = g_expert[t];
    float g = g_gate[t];
    const float4* src = (const float4*)(x + (size_t)t * DD);
    float4* dst = (float4*)(g_expert_in + ((size_t)(e * CAP + s)) * DD);
    float4 v = src[threadIdx.x];          // 256 threads, D/4 = 256
    dst[threadIdx.x] = make_float4(v.x * g, v.y * g, v.z * g, v.w * g);
}

// ---------------- tf32 helpers ----------------
__device__ __forceinline__ uint32_t f2tf(float f) {
    uint32_t r;
    asm("cvt.rna.tf32.f32 %0, %1;" : "=r"(r) : "f"(f));
    return r;
}

// ============================================================================
// Grouped tf32 tensor-core GEMM.
// CTA tile 128x128, BK=32, 256 threads, 8 warps as 4(m) x 2(n),
// warp tile 32x64 = 2 m16-tiles x 8 n8-tiles of m16n8k8 tf32 mma.
// Register-prefetch pipeline: next global tile loads issued before mma stage.
// EPI=0: C = gelu(acc + b1) -> g_h        (A = g_expert_in, per-expert)
// EPI=1: out[tok] = gate * (acc + b2)     (A = g_h, scatter via g_token_of)
// ============================================================================
template<int K, int N, int EPI>
__global__ __launch_bounds__(256)
void gemm_tf32(const float* __restrict__ Bw,    // weights [E, K, N]
               const float* __restrict__ biasb, // [E, N]
               float* __restrict__ out)         // used when EPI==1
{
    const int e = blockIdx.z;
    const float* A = (EPI == 0 ? g_expert_in : g_h) + (size_t)e * CAP * K;
    const float* B = Bw + (size_t)e * K * N;
    const float* bias = biasb + (size_t)e * N;

    const int m_blk = blockIdx.y * 128;
    const int n_blk = blockIdx.x * 128;
    const int tid  = threadIdx.x;
    const int lane = tid & 31;
    const int warp = tid >> 5;
    const int wm = (warp >> 1) * 32;
    const int wn = (warp & 1) * 64;

    __shared__ uint32_t As[32][132];   // [k][m], padded
    __shared__ uint32_t Bs[32][132];   // [k][n], padded (16B-aligned rows)

    float acc[2][8][4];
#pragma unroll
    for (int mt = 0; mt < 2; mt++)
#pragma unroll
        for (int nt = 0; nt < 8; nt++)
#pragma unroll
            for (int r = 0; r < 4; r++) acc[mt][nt][r] = 0.f;

    float4 ga[4], gb[4];
    // prefetch first tile
#pragma unroll
    for (int i = 0; i < 4; i++) {
        int idx = tid + i * 256;
        ga[i] = *(const float4*)(A + (size_t)(m_blk + (idx >> 3)) * K + ((idx & 7) * 4));
        gb[i] = *(const float4*)(B + (size_t)(idx >> 5) * N + n_blk + ((idx & 31) * 4));
    }

    for (int k0 = 0; k0 < K; k0 += 32) {
        // stage prefetched tile into smem (with tf32 rounding)
#pragma unroll
        for (int i = 0; i < 4; i++) {
            int idx = tid + i * 256;
            int ar = idx >> 3, ac = (idx & 7) * 4;
            As[ac + 0][ar] = f2tf(ga[i].x);
            As[ac + 1][ar] = f2tf(ga[i].y);
            As[ac + 2][ar] = f2tf(ga[i].z);
            As[ac + 3][ar] = f2tf(ga[i].w);
            int bk = idx >> 5, bn = (idx & 31) * 4;
            uint4 bv;
            bv.x = f2tf(gb[i].x); bv.y = f2tf(gb[i].y);
            bv.z = f2tf(gb[i].z); bv.w = f2tf(gb[i].w);
            *(uint4*)&Bs[bk][bn] = bv;
        }
        __syncthreads();

        // issue next tile's global loads (latency hidden behind mma)
        if (k0 + 32 < K) {
#pragma unroll
            for (int i = 0; i < 4; i++) {
                int idx = tid + i * 256;
                ga[i] = *(const float4*)(A + (size_t)(m_blk + (idx >> 3)) * K + (k0 + 32) + ((idx & 7) * 4));
                gb[i] = *(const float4*)(B + (size_t)(k0 + 32 + (idx >> 5)) * N + n_blk + ((idx & 31) * 4));
            }
        }

#pragma unroll
        for (int ks = 0; ks < 4; ks++) {
            const int kb = ks * 8;
            uint32_t af[2][4], bf[8][2];
#pragma unroll
            for (int mt = 0; mt < 2; mt++) {
                int r = wm + mt * 16 + (lane >> 2);
                int c = kb + (lane & 3);
                af[mt][0] = As[c][r];
                af[mt][1] = As[c][r + 8];
                af[mt][2] = As[c + 4][r];
                af[mt][3] = As[c + 4][r + 8];
            }
#pragma unroll
            for (int nt = 0; nt < 8; nt++) {
                int n = wn + nt * 8 + (lane >> 2);
                int kk = kb + (lane & 3);
                bf[nt][0] = Bs[kk][n];
                bf[nt][1] = Bs[kk + 4][n];
            }
#pragma unroll
            for (int mt = 0; mt < 2; mt++)
#pragma unroll
                for (int nt = 0; nt < 8; nt++)
                    asm volatile(
                        "mma.sync.aligned.m16n8k8.row.col.f32.tf32.tf32.f32 "
                        "{%0,%1,%2,%3}, {%4,%5,%6,%7}, {%8,%9}, {%0,%1,%2,%3};"
                        : "+f"(acc[mt][nt][0]), "+f"(acc[mt][nt][1]),
                          "+f"(acc[mt][nt][2]), "+f"(acc[mt][nt][3])
                        : "r"(af[mt][0]), "r"(af[mt][1]), "r"(af[mt][2]), "r"(af[mt][3]),
                          "r"(bf[nt][0]), "r"(bf[nt][1]));
        }
        __syncthreads();
    }

    // ---------------- epilogue ----------------
    if (EPI == 0) {
        float* Cp = g_h + (size_t)e * CAP * N;
#pragma unroll
        for (int mt = 0; mt < 2; mt++) {
#pragma unroll
            for (int half = 0; half < 2; half++) {
                int r = m_blk + wm + mt * 16 + (lane >> 2) + half * 8;
#pragma unroll
                for (int nt = 0; nt < 8; nt++) {
                    int col = n_blk + wn + nt * 8 + 2 * (lane & 3);
                    float v0 = acc[mt][nt][half * 2 + 0] + bias[col];
                    float v1 = acc[mt][nt][half * 2 + 1] + bias[col + 1];
                    float o0 = 0.5f * v0 * (1.0f + erff(v0 * 0.70710678118654752f));
                    float o1 = 0.5f * v1 * (1.0f + erff(v1 * 0.70710678118654752f));
                    *(float2*)(Cp + (size_t)r * N + col) = make_float2(o0, o1);
                }
            }
        }
    } else {
#pragma unroll
        for (int mt = 0; mt < 2; mt++) {
#pragma unroll
            for (int half = 0; half < 2; half++) {
                int rl = m_blk + wm + mt * 16 + (lane >> 2) + half * 8; // slot
                int tok = g_token_of[e * CAP + rl];
                if (tok < 0) continue;
                float g = g_gate[tok];   // gate applies a second time (ref quirk)
#pragma unroll
                for (int nt = 0; nt < 8; nt++) {
                    int col = n_blk + wn + nt * 8 + 2 * (lane & 3);
                    float o0 = g * (acc[mt][nt][half * 2 + 0] + bias[col]);
                    float o1 = g * (acc[mt][nt][half * 2 + 1] + bias[col + 1]);
                    *(float2*)(out + (size_t)tok * N + col) = make_float2(o0, o1);
                }
            }
        }
    }
}

// ---------------- launch ----------------
extern "C" void kernel_launch(void* const* d_in, const int* in_sizes, int n_in,
                              void* d_out, int out_size) {
    const float* x  = (const float*)d_in[0];
    const float* wr = (const float*)d_in[1];
    const float* br = (const float*)d_in[2];
    const float* w1 = (const float*)d_in[3];
    const float* b1 = (const float*)d_in[4];
    const float* w2 = (const float*)d_in[5];
    const float* b2 = (const float*)d_in[6];
    float* out = (float*)d_out;

    init_kernel<<<(TT * DD / 4) / 256, 256>>>(out);
    router_kernel<<<TT, 128>>>(x, wr, br);
    scan_kernel<<<1, 256>>>();
    gather_kernel<<<TT, 256>>>(x);

    dim3 g1(FF / 128, CAP / 128, EE);   // 32 x 4 x 8
    gemm_tf32<DD, FF, 0><<<g1, 256>>>(w1, b1, nullptr);
    dim3 g2(DD / 128, CAP / 128, EE);   // 8 x 4 x 8
    gemm_tf32<FF, DD, 1><<<g2, 256>>>(w2, b2, out);
}

// round 6
// speedup vs baseline: 1.2647x; 1.2647x over previous
#include <cuda_runtime.h>
#include <math.h>
#include <stdint.h>

// Problem constants
#define TT   4096      // tokens = B*S
#define DD   1024      // model dim
#define EE   8         // experts
#define FF   4096      // ffn dim
#define CAP  512       // expert capacity

// GEMM tiling
#define BM 128
#define BN 128
#define BK 32
#define STAGES 4
// smem stage geometry (words)
#define A_ROW_W   36                       // 32 + 4 pad (conflict-free frags)
#define A_STAGE_W (BM * A_ROW_W)           // 4608 words = 18432 B
#define B_ROW_W   40                       // 32 + 8 pad
#define B_CHUNK_W (32 * B_ROW_W)           // 1280 words per 32-wide n-chunk
#define B_STAGE_W (4 * B_CHUNK_W)          // 5120 words = 20480 B
#define STAGE_W   (A_STAGE_W + B_STAGE_W)  // 9728 words = 38912 B
#define SMEM_BYTES (STAGES * STAGE_W * 4)  // 155648 B

// ---------------- scratch (device globals; no allocation allowed) ------------
__device__ float g_gate[TT];
__device__ int   g_expert[TT];
__device__ int   g_slot[TT];
__device__ int   g_token_of[EE * CAP];
__device__ float g_expert_in[(size_t)EE * CAP * DD];   // 16.8 MB (tf32 patterns)
__device__ float g_h[(size_t)EE * CAP * FF];           // 67 MB  (tf32 patterns)
// single shared weight scratch: holds tf32(w1) during GEMM1, then tf32(w2)
__device__ float g_wt[(size_t)EE * DD * FF];           // 134 MB (tf32 patterns)

// ---------------- helpers ----------------
__device__ __forceinline__ uint32_t smem_u32(const void* p) {
    uint32_t a;
    asm("{ .reg .u64 t; cvta.to.shared.u64 t, %1; cvt.u32.u64 %0, t; }" : "=r"(a) : "l"(p));
    return a;
}
__device__ __forceinline__ uint32_t f2tf(float f) {
    uint32_t r;
    asm("cvt.rna.tf32.f32 %0, %1;" : "=r"(r) : "f"(f));
    return r;
}

// ---------------- init: zero d_out, token_of = -1 ----------------
__global__ void init_kernel(float* __restrict__ out) {
    int i = blockIdx.x * blockDim.x + threadIdx.x;   // T*D/4 threads
    ((float4*)out)[i] = make_float4(0.f, 0.f, 0.f, 0.f);
    if (i < EE * CAP) g_token_of[i] = -1;
}

// ---------------- weight convert: fp32 -> rna tf32 bit pattern ----------------
__global__ void conv_kernel(const float* __restrict__ src) {
    size_t i = (size_t)blockIdx.x * blockDim.x + threadIdx.x;
    float4 v = ((const float4*)src)[i];
    uint4 o;
    o.x = f2tf(v.x); o.y = f2tf(v.y); o.z = f2tf(v.z); o.w = f2tf(v.w);
    ((uint4*)g_wt)[i] = o;
}

// ---------------- router ----------------
__global__ void router_kernel(const float* __restrict__ x,
                              const float* __restrict__ wr,
                              const float* __restrict__ br) {
    int t = blockIdx.x;
    const float* xt = x + (size_t)t * DD;
    float acc[EE];
#pragma unroll
    for (int e = 0; e < EE; e++) acc[e] = 0.f;
    for (int d = threadIdx.x; d < DD; d += blockDim.x) {
        float xv = xt[d];
        const float4* w = (const float4*)(wr + (size_t)d * EE);
        float4 w0 = w[0], w1 = w[1];
        acc[0] += xv * w0.x; acc[1] += xv * w0.y;
        acc[2] += xv * w0.z; acc[3] += xv * w0.w;
        acc[4] += xv * w1.x; acc[5] += xv * w1.y;
        acc[6] += xv * w1.z; acc[7] += xv * w1.w;
    }
#pragma unroll
    for (int e = 0; e < EE; e++)
#pragma unroll
        for (int o = 16; o > 0; o >>= 1)
            acc[e] += __shfl_down_sync(0xffffffffu, acc[e], o);
    __shared__ float sacc[4][EE];
    int warp = threadIdx.x >> 5, lane = threadIdx.x & 31;
    if (lane == 0)
#pragma unroll
        for (int e = 0; e < EE; e++) sacc[warp][e] = acc[e];
    __syncthreads();
    if (threadIdx.x == 0) {
        float l[EE];
#pragma unroll
        for (int e = 0; e < EE; e++)
            l[e] = sacc[0][e] + sacc[1][e] + sacc[2][e] + sacc[3][e] + br[e];
        float m = l[0]; int am = 0;
#pragma unroll
        for (int e = 1; e < EE; e++) if (l[e] > m) { m = l[e]; am = e; }
        float s = 0.f;
#pragma unroll
        for (int e = 0; e < EE; e++) s += expf(l[e] - m);
        g_gate[t]   = 1.f / s;
        g_expert[t] = am;
    }
}

// ---------------- scan: token-order positions per expert ----------------
__global__ void scan_kernel() {
    __shared__ int scnt[256][EE];
    int tid = threadIdx.x;
    int cnt[EE];
#pragma unroll
    for (int e = 0; e < EE; e++) cnt[e] = 0;
    int base_t = tid * 16;
    for (int i = 0; i < 16; i++) cnt[g_expert[base_t + i]]++;
#pragma unroll
    for (int e = 0; e < EE; e++) scnt[tid][e] = cnt[e];
    __syncthreads();
    if (tid < EE) {
        int run = 0;
        for (int i = 0; i < 256; i++) { int v = scnt[i][tid]; scnt[i][tid] = run; run += v; }
    }
    __syncthreads();
    int pos[EE];
#pragma unroll
    for (int e = 0; e < EE; e++) pos[e] = scnt[tid][e];
    for (int i = 0; i < 16; i++) {
        int t = base_t + i;
        int e = g_expert[t];
        int p = ++pos[e];                 // 1-based position (reference quirk)
        if (p < CAP) { g_slot[t] = p; g_token_of[e * CAP + p] = t; }
        else         { g_slot[t] = -1; }
    }
}

// ---------------- gather: expert_in[e, slot] = rna_tf32(gate * x[t]) --------
__global__ void gather_kernel(const float* __restrict__ x) {
    int t = blockIdx.x;
    int s = g_slot[t];
    if (s < 0) return;
    int e = g_expert[t];
    float g = g_gate[t];
    const float4* src = (const float4*)(x + (size_t)t * DD);
    uint4* dst = (uint4*)(g_expert_in + ((size_t)(e * CAP + s)) * DD);
    float4 v = src[threadIdx.x];
    uint4 o;
    o.x = f2tf(v.x * g); o.y = f2tf(v.y * g); o.z = f2tf(v.z * g); o.w = f2tf(v.w * g);
    dst[threadIdx.x] = o;
}

// ============================================================================
// Legacy-mma tf32 grouped GEMM, pure cp.async 4-stage pipeline.
// CTA tile 128x128, BK=32, 256 threads = 8 warps (4m x 2n), warp tile 32x64,
// m16n8k8 tf32 mma. All operands are pre-rounded tf32 bit patterns in gmem.
// EPI=0: g_h = tf32(gelu(acc + b1))   EPI=1: out[tok] = gate*(acc + b2)
// ============================================================================
template<int K, int NTOT, int EPI>
__global__ void __launch_bounds__(256, 1)
gemm_tc(const float* __restrict__ biasb, float* __restrict__ outp) {
    constexpr int NCHUNK = K / BK;

    const int e = blockIdx.z;
    const int m_blk = blockIdx.y * BM;
    const int n_blk = blockIdx.x * BN;
    const float* A  = (EPI == 0 ? g_expert_in : g_h) + (size_t)e * CAP * K;
    const float* Bg = g_wt + (size_t)e * K * NTOT;
    const float* bias = biasb + (size_t)e * NTOT;

    extern __shared__ float smem[];
    const uint32_t sbase = smem_u32(smem);
    const uint32_t* smem32 = (const uint32_t*)smem;

    const int tid = threadIdx.x, lane = tid & 31, warp = tid >> 5;
    const int wm = (warp >> 1) * 32;
    const int wn = (warp & 1) * 64;

    // per-thread load coordinates (4 chunks of A, 4 of B per stage)
    int a_m[4], a_j[4], b_kr[4], b_n4[4];
    uint32_t a_dst[4], b_dst[4];
#pragma unroll
    for (int i = 0; i < 4; i++) {
        int idx = tid + i * 256;
        a_m[i] = idx >> 3; a_j[i] = (idx & 7) * 4;
        a_dst[i] = (uint32_t)((a_m[i] * A_ROW_W + a_j[i]) * 4);
        b_kr[i] = idx >> 5; b_n4[i] = idx & 31;
        int chunk = b_n4[i] >> 3, jw = (b_n4[i] & 7) * 4;
        b_dst[i] = (uint32_t)((A_STAGE_W + chunk * B_CHUNK_W + b_kr[i] * B_ROW_W + jw) * 4);
    }

#define ISSUE_CHUNK(c) do { \
    uint32_t stb = sbase + (uint32_t)(((c) & (STAGES - 1)) * STAGE_W * 4); \
    _Pragma("unroll") \
    for (int i = 0; i < 4; i++) { \
        const float* srcA = A + (size_t)(m_blk + a_m[i]) * K + (c) * BK + a_j[i]; \
        asm volatile("cp.async.cg.shared.global [%0], [%1], 16;" \
                     :: "r"(stb + a_dst[i]), "l"(srcA) : "memory"); \
        const float* srcB = Bg + (size_t)((c) * BK + b_kr[i]) * NTOT + n_blk + b_n4[i] * 4; \
        asm volatile("cp.async.cg.shared.global [%0], [%1], 16;" \
                     :: "r"(stb + b_dst[i]), "l"(srcB) : "memory"); \
    } \
} while (0)

    float acc[2][8][4];
#pragma unroll
    for (int mt = 0; mt < 2; mt++)
#pragma unroll
        for (int nt = 0; nt < 8; nt++)
#pragma unroll
            for (int r = 0; r < 4; r++) acc[mt][nt][r] = 0.f;

    // prologue: stages 0..2
#pragma unroll
    for (int c = 0; c < STAGES - 1; c++) {
        ISSUE_CHUNK(c);
        asm volatile("cp.async.commit_group;" ::: "memory");
    }

    for (int c = 0; c < NCHUNK; c++) {
        asm volatile("cp.async.wait_group %0;" :: "n"(STAGES - 2) : "memory");
        __syncthreads();
        if (c + STAGES - 1 < NCHUNK) ISSUE_CHUNK(c + STAGES - 1);
        asm volatile("cp.async.commit_group;" ::: "memory");

        const uint32_t* As = smem32 + (c & (STAGES - 1)) * STAGE_W;
        const uint32_t* Bs = As + A_STAGE_W;
#pragma unroll
        for (int ks = 0; ks < 4; ks++) {
            uint32_t af[2][4], bf[8][2];
            const int ck = ks * 8 + (lane & 3);
#pragma unroll
            for (int mt = 0; mt < 2; mt++) {
                int r = wm + mt * 16 + (lane >> 2);
                af[mt][0] = As[r * A_ROW_W + ck];
                af[mt][1] = As[(r + 8) * A_ROW_W + ck];
                af[mt][2] = As[r * A_ROW_W + ck + 4];
                af[mt][3] = As[(r + 8) * A_ROW_W + ck + 4];
            }
#pragma unroll
            for (int nt = 0; nt < 8; nt++) {
                int n = wn + nt * 8 + (lane >> 2);
                const uint32_t* Bc = Bs + (n >> 5) * B_CHUNK_W;
                int nn = n & 31;
                bf[nt][0] = Bc[ck * B_ROW_W + nn];
                bf[nt][1] = Bc[(ck + 4) * B_ROW_W + nn];
            }
#pragma unroll
            for (int mt = 0; mt < 2; mt++)
#pragma unroll
                for (int nt = 0; nt < 8; nt++)
                    asm volatile(
                        "mma.sync.aligned.m16n8k8.row.col.f32.tf32.tf32.f32 "
                        "{%0,%1,%2,%3}, {%4,%5,%6,%7}, {%8,%9}, {%0,%1,%2,%3};"
                        : "+f"(acc[mt][nt][0]), "+f"(acc[mt][nt][1]),
                          "+f"(acc[mt][nt][2]), "+f"(acc[mt][nt][3])
                        : "r"(af[mt][0]), "r"(af[mt][1]), "r"(af[mt][2]), "r"(af[mt][3]),
                          "r"(bf[nt][0]), "r"(bf[nt][1]));
        }
        __syncthreads();
    }
#undef ISSUE_CHUNK

    // ---------------- epilogue ----------------
    if (EPI == 0) {
#pragma unroll
        for (int mt = 0; mt < 2; mt++) {
#pragma unroll
            for (int half = 0; half < 2; half++) {
                int r = m_blk + wm + mt * 16 + (lane >> 2) + half * 8;
                float* Cp = g_h + (size_t)e * CAP * NTOT + (size_t)r * NTOT;
#pragma unroll
                for (int nt = 0; nt < 8; nt++) {
                    int col = n_blk + wn + nt * 8 + 2 * (lane & 3);
                    float v0 = acc[mt][nt][half * 2 + 0] + bias[col];
                    float v1 = acc[mt][nt][half * 2 + 1] + bias[col + 1];
                    uint32_t o0 = f2tf(0.5f * v0 * (1.0f + erff(v0 * 0.70710678118654752f)));
                    uint32_t o1 = f2tf(0.5f * v1 * (1.0f + erff(v1 * 0.70710678118654752f)));
                    uint2 o; o.x = o0; o.y = o1;
                    *(uint2*)(Cp + col) = o;
                }
            }
        }
    } else {
#pragma unroll
        for (int mt = 0; mt < 2; mt++) {
#pragma unroll
            for (int half = 0; half < 2; half++) {
                int rl = m_blk + wm + mt * 16 + (lane >> 2) + half * 8;  // slot
                int tok = g_token_of[e * CAP + rl];
                if (tok < 0) continue;
                float g = g_gate[tok];   // gate applies a second time (ref quirk)
#pragma unroll
                for (int nt = 0; nt < 8; nt++) {
                    int col = n_blk + wn + nt * 8 + 2 * (lane & 3);
                    float o0 = g * (acc[mt][nt][half * 2 + 0] + bias[col]);
                    float o1 = g * (acc[mt][nt][half * 2 + 1] + bias[col + 1]);
                    *(float2*)(outp + (size_t)tok * NTOT + col) = make_float2(o0, o1);
                }
            }
        }
    }
}

// ---------------- launch ----------------
extern "C" void kernel_launch(void* const* d_in, const int* in_sizes, int n_in,
                              void* d_out, int out_size) {
    const float* x  = (const float*)d_in[0];
    const float* wr = (const float*)d_in[1];
    const float* br = (const float*)d_in[2];
    const float* w1 = (const float*)d_in[3];
    const float* b1 = (const float*)d_in[4];
    const float* w2 = (const float*)d_in[5];
    const float* b2 = (const float*)d_in[6];
    float* out = (float*)d_out;

    static bool attr_set = false;
    if (!attr_set) {
        cudaFuncSetAttribute(gemm_tc<DD, FF, 0>, cudaFuncAttributeMaxDynamicSharedMemorySize, SMEM_BYTES);
        cudaFuncSetAttribute(gemm_tc<FF, DD, 1>, cudaFuncAttributeMaxDynamicSharedMemorySize, SMEM_BYTES);
        attr_set = true;
    }

    init_kernel<<<(TT * DD / 4) / 256, 256>>>(out);
    router_kernel<<<TT, 128>>>(x, wr, br);
    scan_kernel<<<1, 256>>>();
    gather_kernel<<<TT, 256>>>(x);

    // GEMM1 (w1 converted into shared scratch, then consumed)
    conv_kernel<<<(int)(((size_t)EE * DD * FF / 4) / 256), 256>>>(w1);
    dim3 g1(FF / 128, CAP / 128, EE);   // 32 x 4 x 8 = 1024 CTAs
    gemm_tc<DD, FF, 0><<<g1, 256, SMEM_BYTES>>>(b1, nullptr);

    // GEMM2 (scratch reused for w2 — stream order makes this safe)
    conv_kernel<<<(int)(((size_t)EE * FF * DD / 4) / 256), 256>>>(w2);
    dim3 g2(DD / 128, CAP / 128, EE);   // 8 x 4 x 8 = 256 CTAs
    gemm_tc<FF, DD, 1><<<g2, 256, SMEM_BYTES>>>(b2, out);
}

// round 7
// speedup vs baseline: 1.4932x; 1.1807x over previous
#include <cuda_runtime.h>
#include <math.h>
#include <stdint.h>

// Problem constants
#define TT   4096      // tokens = B*S
#define DD   1024      // model dim
#define EE   8         // experts
#define FF   4096      // ffn dim
#define CAP  512       // expert capacity

// GEMM tiling
#define BM 128
#define BN 128
#define BK 32
#define STAGES 2
// smem stage geometry (words)
#define A_ROW_W   36                       // 32 + 4 pad (conflict-free frags)
#define A_STAGE_W (BM * A_ROW_W)           // 4608 words = 18432 B
#define B_ROW_W   40                       // 32 + 8 pad
#define B_CHUNK_W (32 * B_ROW_W)           // 1280 words per 32-wide n-chunk
#define B_STAGE_W (4 * B_CHUNK_W)          // 5120 words = 20480 B
#define STAGE_W   (A_STAGE_W + B_STAGE_W)  // 9728 words = 38912 B
#define SMEM_BYTES (STAGES * STAGE_W * 4)  // 77824 B  -> 2 CTAs/SM

// ---------------- scratch (device globals; no allocation allowed) ------------
__device__ float g_gate[TT];
__device__ int   g_expert[TT];
__device__ int   g_slot[TT];
__device__ int   g_token_of[EE * CAP];
__device__ float g_expert_in[(size_t)EE * CAP * DD];   // 16.8 MB (tf32 patterns)
__device__ float g_h[(size_t)EE * CAP * FF];           // 67 MB  (tf32 patterns)

// ---------------- helpers ----------------
__device__ __forceinline__ uint32_t smem_u32(const void* p) {
    uint32_t a;
    asm("{ .reg .u64 t; cvta.to.shared.u64 t, %1; cvt.u32.u64 %0, t; }" : "=r"(a) : "l"(p));
    return a;
}
__device__ __forceinline__ uint32_t f2tf(float f) {
    uint32_t r;
    asm("cvt.rna.tf32.f32 %0, %1;" : "=r"(r) : "f"(f));
    return r;
}

// ---------------- init: zero d_out, token_of = -1 ----------------
__global__ void init_kernel(float* __restrict__ out) {
    int i = blockIdx.x * blockDim.x + threadIdx.x;   // T*D/4 threads
    ((float4*)out)[i] = make_float4(0.f, 0.f, 0.f, 0.f);
    if (i < EE * CAP) g_token_of[i] = -1;
}

// ---------------- router ----------------
__global__ void router_kernel(const float* __restrict__ x,
                              const float* __restrict__ wr,
                              const float* __restrict__ br) {
    int t = blockIdx.x;
    const float* xt = x + (size_t)t * DD;
    float acc[EE];
#pragma unroll
    for (int e = 0; e < EE; e++) acc[e] = 0.f;
    for (int d = threadIdx.x; d < DD; d += blockDim.x) {
        float xv = xt[d];
        const float4* w = (const float4*)(wr + (size_t)d * EE);
        float4 w0 = w[0], w1 = w[1];
        acc[0] += xv * w0.x; acc[1] += xv * w0.y;
        acc[2] += xv * w0.z; acc[3] += xv * w0.w;
        acc[4] += xv * w1.x; acc[5] += xv * w1.y;
        acc[6] += xv * w1.z; acc[7] += xv * w1.w;
    }
#pragma unroll
    for (int e = 0; e < EE; e++)
#pragma unroll
        for (int o = 16; o > 0; o >>= 1)
            acc[e] += __shfl_down_sync(0xffffffffu, acc[e], o);
    __shared__ float sacc[4][EE];
    int warp = threadIdx.x >> 5, lane = threadIdx.x & 31;
    if (lane == 0)
#pragma unroll
        for (int e = 0; e < EE; e++) sacc[warp][e] = acc[e];
    __syncthreads();
    if (threadIdx.x == 0) {
        float l[EE];
#pragma unroll
        for (int e = 0; e < EE; e++)
            l[e] = sacc[0][e] + sacc[1][e] + sacc[2][e] + sacc[3][e] + br[e];
        float m = l[0]; int am = 0;
#pragma unroll
        for (int e = 1; e < EE; e++) if (l[e] > m) { m = l[e]; am = e; }
        float s = 0.f;
#pragma unroll
        for (int e = 0; e < EE; e++) s += expf(l[e] - m);
        g_gate[t]   = 1.f / s;
        g_expert[t] = am;
    }
}

// ---------------- scan: token-order positions per expert ----------------
__global__ void scan_kernel() {
    __shared__ int scnt[256][EE];
    int tid = threadIdx.x;
    int cnt[EE];
#pragma unroll
    for (int e = 0; e < EE; e++) cnt[e] = 0;
    int base_t = tid * 16;
    for (int i = 0; i < 16; i++) cnt[g_expert[base_t + i]]++;
#pragma unroll
    for (int e = 0; e < EE; e++) scnt[tid][e] = cnt[e];
    __syncthreads();
    if (tid < EE) {
        int run = 0;
        for (int i = 0; i < 256; i++) { int v = scnt[i][tid]; scnt[i][tid] = run; run += v; }
    }
    __syncthreads();
    int pos[EE];
#pragma unroll
    for (int e = 0; e < EE; e++) pos[e] = scnt[tid][e];
    for (int i = 0; i < 16; i++) {
        int t = base_t + i;
        int e = g_expert[t];
        int p = ++pos[e];                 // 1-based position (reference quirk)
        if (p < CAP) { g_slot[t] = p; g_token_of[e * CAP + p] = t; }
        else         { g_slot[t] = -1; }
    }
}

// ---------------- gather: expert_in[e, slot] = rna_tf32(gate * x[t]) --------
__global__ void gather_kernel(const float* __restrict__ x) {
    int t = blockIdx.x;
    int s = g_slot[t];
    if (s < 0) return;
    int e = g_expert[t];
    float g = g_gate[t];
    const float4* src = (const float4*)(x + (size_t)t * DD);
    uint4* dst = (uint4*)(g_expert_in + ((size_t)(e * CAP + s)) * DD);
    float4 v = src[threadIdx.x];
    uint4 o;
    o.x = f2tf(v.x * g); o.y = f2tf(v.y * g); o.z = f2tf(v.z * g); o.w = f2tf(v.w * g);
    dst[threadIdx.x] = o;
}

// ============================================================================
// Legacy-mma tf32 grouped GEMM, cp.async 2-stage pipeline, 2 CTAs/SM.
// CTA tile 128x128, BK=32, 256 threads = 8 warps (4m x 2n), warp tile 32x64,
// m16n8k8 tf32 mma. A operand is pre-rounded tf32 patterns; B (weights) is
// staged raw fp32 and rounded (cvt.rna.tf32) at fragment-load time — numerics
// identical to pre-converted weights, zero extra gmem traffic.
// EPI=0: g_h = tf32(gelu(acc + b1))   EPI=1: out[tok] = gate*(acc + b2)
// ============================================================================
template<int K, int NTOT, int EPI>
__global__ void __launch_bounds__(256, 2)
gemm_tc(const float* __restrict__ Bw, const float* __restrict__ biasb,
        float* __restrict__ outp) {
    constexpr int NCHUNK = K / BK;

    const int e = blockIdx.z;
    const int m_blk = blockIdx.y * BM;
    const int n_blk = blockIdx.x * BN;
    const float* A  = (EPI == 0 ? g_expert_in : g_h) + (size_t)e * CAP * K;
    const float* Bg = Bw + (size_t)e * K * NTOT;
    const float* bias = biasb + (size_t)e * NTOT;

    extern __shared__ float smem[];
    const uint32_t sbase = smem_u32(smem);
    const uint32_t* smem32 = (const uint32_t*)smem;

    const int tid = threadIdx.x, lane = tid & 31, warp = tid >> 5;
    const int wm = (warp >> 1) * 32;
    const int wn = (warp & 1) * 64;

// per-thread load coordinates derived inline (minimal register footprint):
// idx = tid + i*256; A: m=idx>>3, j=(idx&7)*4 ; B: kr=idx>>5, n4=idx&31
#define ISSUE_CHUNK(c) do { \
    uint32_t stb = sbase + (uint32_t)(((c) & (STAGES - 1)) * STAGE_W * 4); \
    _Pragma("unroll") \
    for (int i = 0; i < 4; i++) { \
        int idx = tid + i * 256; \
        int am = idx >> 3, aj = (idx & 7) * 4; \
        const float* srcA = A + (size_t)(m_blk + am) * K + (c) * BK + aj; \
        asm volatile("cp.async.cg.shared.global [%0], [%1], 16;" \
                     :: "r"(stb + (uint32_t)((am * A_ROW_W + aj) * 4)), "l"(srcA) : "memory"); \
        int bkr = idx >> 5, bn4 = idx & 31; \
        int bch = bn4 >> 3, bjw = (bn4 & 7) * 4; \
        const float* srcB = Bg + (size_t)((c) * BK + bkr) * NTOT + n_blk + bn4 * 4; \
        asm volatile("cp.async.cg.shared.global [%0], [%1], 16;" \
                     :: "r"(stb + (uint32_t)((A_STAGE_W + bch * B_CHUNK_W + bkr * B_ROW_W + bjw) * 4)), \
                        "l"(srcB) : "memory"); \
    } \
} while (0)

    float acc[2][8][4];
#pragma unroll
    for (int mt = 0; mt < 2; mt++)
#pragma unroll
        for (int nt = 0; nt < 8; nt++)
#pragma unroll
            for (int r = 0; r < 4; r++) acc[mt][nt][r] = 0.f;

    // prologue: stage 0
    ISSUE_CHUNK(0);
    asm volatile("cp.async.commit_group;" ::: "memory");

    for (int c = 0; c < NCHUNK; c++) {
        if (c + 1 < NCHUNK) {
            ISSUE_CHUNK(c + 1);
            asm volatile("cp.async.commit_group;" ::: "memory");
            asm volatile("cp.async.wait_group 1;" ::: "memory");
        } else {
            asm volatile("cp.async.wait_group 0;" ::: "memory");
        }
        __syncthreads();

        const uint32_t* As = smem32 + (c & (STAGES - 1)) * STAGE_W;
        const uint32_t* Bs = As + A_STAGE_W;
#pragma unroll
        for (int ks = 0; ks < 4; ks++) {
            uint32_t af[2][4], bf[8][2];
            const int ck = ks * 8 + (lane & 3);
#pragma unroll
            for (int mt = 0; mt < 2; mt++) {
                int r = wm + mt * 16 + (lane >> 2);
                af[mt][0] = As[r * A_ROW_W + ck];
                af[mt][1] = As[(r + 8) * A_ROW_W + ck];
                af[mt][2] = As[r * A_ROW_W + ck + 4];
                af[mt][3] = As[(r + 8) * A_ROW_W + ck + 4];
            }
#pragma unroll
            for (int nt = 0; nt < 8; nt++) {
                int n = wn + nt * 8 + (lane >> 2);
                const uint32_t* Bc = Bs + (n >> 5) * B_CHUNK_W;
                int nn = n & 31;
                // weights staged raw fp32 -> round-to-nearest tf32 at use
                bf[nt][0] = f2tf(__uint_as_float(Bc[ck * B_ROW_W + nn]));
                bf[nt][1] = f2tf(__uint_as_float(Bc[(ck + 4) * B_ROW_W + nn]));
            }
#pragma unroll
            for (int mt = 0; mt < 2; mt++)
#pragma unroll
                for (int nt = 0; nt < 8; nt++)
                    asm volatile(
                        "mma.sync.aligned.m16n8k8.row.col.f32.tf32.tf32.f32 "
                        "{%0,%1,%2,%3}, {%4,%5,%6,%7}, {%8,%9}, {%0,%1,%2,%3};"
                        : "+f"(acc[mt][nt][0]), "+f"(acc[mt][nt][1]),
                          "+f"(acc[mt][nt][2]), "+f"(acc[mt][nt][3])
                        : "r"(af[mt][0]), "r"(af[mt][1]), "r"(af[mt][2]), "r"(af[mt][3]),
                          "r"(bf[nt][0]), "r"(bf[nt][1]));
        }
        __syncthreads();
    }
#undef ISSUE_CHUNK

    // ---------------- epilogue ----------------
    if (EPI == 0) {
#pragma unroll
        for (int mt = 0; mt < 2; mt++) {
#pragma unroll
            for (int half = 0; half < 2; half++) {
                int r = m_blk + wm + mt * 16 + (lane >> 2) + half * 8;
                float* Cp = g_h + (size_t)e * CAP * NTOT + (size_t)r * NTOT;
#pragma unroll
                for (int nt = 0; nt < 8; nt++) {
                    int col = n_blk + wn + nt * 8 + 2 * (lane & 3);
                    float v0 = acc[mt][nt][half * 2 + 0] + bias[col];
                    float v1 = acc[mt][nt][half * 2 + 1] + bias[col + 1];
                    uint32_t o0 = f2tf(0.5f * v0 * (1.0f + erff(v0 * 0.70710678118654752f)));
                    uint32_t o1 = f2tf(0.5f * v1 * (1.0f + erff(v1 * 0.70710678118654752f)));
                    uint2 o; o.x = o0; o.y = o1;
                    *(uint2*)(Cp + col) = o;
                }
            }
        }
    } else {
#pragma unroll
        for (int mt = 0; mt < 2; mt++) {
#pragma unroll
            for (int half = 0; half < 2; half++) {
                int rl = m_blk + wm + mt * 16 + (lane >> 2) + half * 8;  // slot
                int tok = g_token_of[e * CAP + rl];
                if (tok < 0) continue;
                float g = g_gate[tok];   // gate applies a second time (ref quirk)
#pragma unroll
                for (int nt = 0; nt < 8; nt++) {
                    int col = n_blk + wn + nt * 8 + 2 * (lane & 3);
                    float o0 = g * (acc[mt][nt][half * 2 + 0] + bias[col]);
                    float o1 = g * (acc[mt][nt][half * 2 + 1] + bias[col + 1]);
                    *(float2*)(outp + (size_t)tok * NTOT + col) = make_float2(o0, o1);
                }
            }
        }
    }
}

// ---------------- launch ----------------
extern "C" void kernel_launch(void* const* d_in, const int* in_sizes, int n_in,
                              void* d_out, int out_size) {
    const float* x  = (const float*)d_in[0];
    const float* wr = (const float*)d_in[1];
    const float* br = (const float*)d_in[2];
    const float* w1 = (const float*)d_in[3];
    const float* b1 = (const float*)d_in[4];
    const float* w2 = (const float*)d_in[5];
    const float* b2 = (const float*)d_in[6];
    float* out = (float*)d_out;

    static bool attr_set = false;
    if (!attr_set) {
        cudaFuncSetAttribute(gemm_tc<DD, FF, 0>, cudaFuncAttributeMaxDynamicSharedMemorySize, SMEM_BYTES);
        cudaFuncSetAttribute(gemm_tc<FF, DD, 1>, cudaFuncAttributeMaxDynamicSharedMemorySize, SMEM_BYTES);
        attr_set = true;
    }

    init_kernel<<<(TT * DD / 4) / 256, 256>>>(out);
    router_kernel<<<TT, 128>>>(x, wr, br);
    scan_kernel<<<1, 256>>>();
    gather_kernel<<<TT, 256>>>(x);

    dim3 g1(FF / 128, CAP / 128, EE);   // 32 x 4 x 8 = 1024 CTAs
    gemm_tc<DD, FF, 0><<<g1, 256, SMEM_BYTES>>>(w1, b1, nullptr);
    dim3 g2(DD / 128, CAP / 128, EE);   // 8 x 4 x 8 = 256 CTAs
    gemm_tc<FF, DD, 1><<<g2, 256, SMEM_BYTES>>>(w2, b2, out);
}